// round 2
// baseline (speedup 1.0000x reference)
#include <cuda_runtime.h>
#include <cstdint>

// Problem constants
#define NR 50000      // rows (N)
#define HH 4          // heads
#define DM 256        // D_MODEL (= 2*D_IN)
#define DHEAD 1024    // H * D_MODEL
#define NCLS 40       // classes

// Scratch (static device allocations — no cudaMalloc allowed)
__device__ float g_w[HH * NR];                      // w[h][j] = value applied to output row j of head h
__device__ float g_wgk[DHEAD * NCLS];               // gamma[k] * W_head[k][o]  (k-major, pitch 40)
__device__ float g_cvec[NCLS];                      // beta @ W_head + b_head
__device__ float g_u[(size_t)NR * DHEAD];           // normalized concat activations

// ---------------------------------------------------------------------------
// Prep: scatter permutation values by COLUMN index (perm^T composition),
// fold gamma into W_head, fold beta@W_head + b_head.
// ---------------------------------------------------------------------------
__global__ void prep_kernel(const int* __restrict__ idx, const float* __restrict__ vals,
                            const float* __restrict__ gamma, const float* __restrict__ beta,
                            const float* __restrict__ Wh, const float* __restrict__ bh) {
    int t = blockIdx.x * blockDim.x + threadIdx.x;
    const int NNZ = HH * NR;
    if (t < NNZ) {
        int b = idx[t];                 // indices[0][t]
        int j = idx[2 * NNZ + t];       // indices[2][t] = sigma_b(i) — the column
        g_w[b * NR + j] = vals[t];
    }
    if (t < DHEAD * NCLS) {
        int k = t / NCLS;
        g_wgk[t] = gamma[k] * Wh[t];    // W_head is (1024,40) row-major == k-major already
    }
    if (t < NCLS) {
        float s = bh[t];
        for (int k = 0; k < DHEAD; k++) s += beta[k] * Wh[k * NCLS + t];
        g_cvec[t] = s;
    }
}

// ---------------------------------------------------------------------------
// Main fused kernel: per block of 16 rows:
//   Z = feat @ W_in   (thread owns one output column c, 16 rows in f32x2 pairs)
//   u[h] = w_h * relu(w_h * Z + b_in)   for h=0..3
//   LayerNorm stats over the 1024-wide concat (block reduction)
//   write normalized u to gmem
// ---------------------------------------------------------------------------
__global__ __launch_bounds__(256) void main_kernel(
    const float* __restrict__ features, const float* __restrict__ appd,
    const float* __restrict__ Win, const float* __restrict__ bin)
{
    __shared__ float feat_s[256 * 18];   // [k][r] transposed, pitch 18 (even -> 8B pair alignment)
    __shared__ float w_s[4 * 16];        // w[h][r] for this row tile
    __shared__ float redS[8][16];
    __shared__ float redQ[8][16];
    __shared__ float mu_s[16], rs_s[16];

    const int c = threadIdx.x;           // output column 0..255 (also feat index k on load)
    const int j0 = blockIdx.x * 16;

    // Load feat tile transposed: feat[k][r]. k<128 -> features, k>=128 -> appd (concat).
    {
        const float* src = (c < 128) ? (features + (size_t)j0 * 128 + c)
                                     : (appd + (size_t)j0 * 128 + (c - 128));
        #pragma unroll
        for (int r = 0; r < 16; r++)
            feat_s[c * 18 + r] = src[(size_t)r * 128];
    }
    if (c < 64) {
        int h = c >> 4, r = c & 15;
        w_s[c] = g_w[h * NR + j0 + r];
    }
    __syncthreads();

    // ---- Z-GEMM: acc[r] = sum_k feat[k][r] * W_in[k][c], rows paired for f32x2 ----
    unsigned long long zacc[8];
    #pragma unroll
    for (int p = 0; p < 8; p++) zacc[p] = 0ULL;   // (0.f, 0.f)

    const float* wcol = Win + c;
    #pragma unroll 8
    for (int k = 0; k < 256; k++) {
        float wv = __ldg(wcol + k * 256);
        unsigned long long wv2;
        asm("mov.b64 %0, {%1, %1};" : "=l"(wv2) : "f"(wv));
        const unsigned long long* fp = (const unsigned long long*)&feat_s[k * 18];
        #pragma unroll
        for (int p = 0; p < 8; p++)
            asm("fma.rn.f32x2 %0, %1, %2, %0;" : "+l"(zacc[p]) : "l"(fp[p]), "l"(wv2));
    }

    float z[16];
    #pragma unroll
    for (int p = 0; p < 8; p++)
        asm("mov.b64 {%0, %1}, %2;" : "=f"(z[2 * p]), "=f"(z[2 * p + 1]) : "l"(zacc[p]));

    // ---- activation + LN stats ----
    const float bi = __ldg(bin + c);
    float ps[16], pq[16];
    #pragma unroll
    for (int r = 0; r < 16; r++) {
        float s = 0.f, q = 0.f;
        #pragma unroll
        for (int h = 0; h < 4; h++) {
            float w = w_s[h * 16 + r];
            float u = w * fmaxf(fmaf(w, z[r], bi), 0.f);
            s += u; q += u * u;
        }
        ps[r] = s; pq[r] = q;
    }
    #pragma unroll
    for (int r = 0; r < 16; r++) {
        float s = ps[r], q = pq[r];
        #pragma unroll
        for (int o = 16; o; o >>= 1) {
            s += __shfl_xor_sync(0xffffffffu, s, o);
            q += __shfl_xor_sync(0xffffffffu, q, o);
        }
        ps[r] = s; pq[r] = q;
    }
    const int lane = c & 31, wid = c >> 5;
    if (lane == 0) {
        #pragma unroll
        for (int r = 0; r < 16; r++) { redS[wid][r] = ps[r]; redQ[wid][r] = pq[r]; }
    }
    __syncthreads();
    if (c < 16) {
        float s = 0.f, q = 0.f;
        #pragma unroll
        for (int w = 0; w < 8; w++) { s += redS[w][c]; q += redQ[w][c]; }
        float mu = s * (1.f / 1024.f);
        float var = q * (1.f / 1024.f) - mu * mu;
        mu_s[c] = mu;
        rs_s[c] = rsqrtf(var + 1e-5f);
    }
    __syncthreads();

    // ---- recompute u, normalize, write (coalesced across c) ----
    #pragma unroll
    for (int r = 0; r < 16; r++) {
        float mu = mu_s[r], rs = rs_s[r];
        float* urow = g_u + (size_t)(j0 + r) * DHEAD + c;
        #pragma unroll
        for (int h = 0; h < 4; h++) {
            float w = w_s[h * 16 + r];
            float u = w * fmaxf(fmaf(w, z[r], bi), 0.f);
            urow[h * 256] = (u - mu) * rs;
        }
    }
}

// ---------------------------------------------------------------------------
// Head GEMM: out[j][o] = sum_k u[j][k] * wgk[k][o] + cvec[o]
// 80 rows/block, 320 threads: thread = (o = t%40, row-group rg = t/40 owning 10 rows),
// K staged in smem chunks of 128 (u transposed so row-pairs are f32x2-adjacent).
// ---------------------------------------------------------------------------
__global__ __launch_bounds__(320) void head_kernel(float* __restrict__ out)
{
    __shared__ float u_s[128 * 82];     // [kk][r], pitch 82 (even, conflict-friendly)
    __shared__ float wg_s[128 * 40];    // [kk][o]

    const int t = threadIdx.x;
    const int j0 = blockIdx.x * 80;
    const int o = t % 40;
    const int rg = t / 40;              // 0..7, owns rows rg*10 .. rg*10+9

    unsigned long long acc[5];
    #pragma unroll
    for (int p = 0; p < 5; p++) acc[p] = 0ULL;

    for (int kc = 0; kc < 8; kc++) {
        const int k0 = kc * 128;
        __syncthreads();
        // stage u chunk (transposed)
        for (int idx = t; idx < 128 * 80; idx += 320) {
            int r = idx / 128, kk = idx % 128;
            u_s[kk * 82 + r] = g_u[(size_t)(j0 + r) * DHEAD + k0 + kk];
        }
        // stage wg chunk
        for (int idx = t; idx < 128 * 40; idx += 320)
            wg_s[idx] = g_wgk[k0 * 40 + idx];
        __syncthreads();

        #pragma unroll 4
        for (int kk = 0; kk < 128; kk++) {
            float wv = wg_s[kk * 40 + o];
            unsigned long long wv2;
            asm("mov.b64 %0, {%1, %1};" : "=l"(wv2) : "f"(wv));
            const unsigned long long* up = (const unsigned long long*)&u_s[kk * 82 + rg * 10];
            #pragma unroll
            for (int p = 0; p < 5; p++)
                asm("fma.rn.f32x2 %0, %1, %2, %0;" : "+l"(acc[p]) : "l"(up[p]), "l"(wv2));
        }
    }

    const float cv = g_cvec[o];
    #pragma unroll
    for (int p = 0; p < 5; p++) {
        float a0, a1;
        asm("mov.b64 {%0, %1}, %2;" : "=f"(a0), "=f"(a1) : "l"(acc[p]));
        int r = rg * 10 + 2 * p;
        out[(size_t)(j0 + r) * NCLS + o] = a0 + cv;
        out[(size_t)(j0 + r + 1) * NCLS + o] = a1 + cv;
    }
}

// ---------------------------------------------------------------------------
extern "C" void kernel_launch(void* const* d_in, const int* in_sizes, int n_in,
                              void* d_out, int out_size) {
    const int*   perm_idx  = (const int*)d_in[0];
    const float* perm_vals = (const float*)d_in[1];
    const float* features  = (const float*)d_in[2];
    const float* appd      = (const float*)d_in[3];
    const float* Win       = (const float*)d_in[4];
    const float* bin       = (const float*)d_in[5];
    const float* gamma     = (const float*)d_in[6];
    const float* beta      = (const float*)d_in[7];
    const float* Whead     = (const float*)d_in[8];
    const float* bhead     = (const float*)d_in[9];
    float* out = (float*)d_out;

    prep_kernel<<<(HH * NR + 255) / 256, 256>>>(perm_idx, perm_vals, gamma, beta, Whead, bhead);
    main_kernel<<<NR / 16, 256>>>(features, appd, Win, bin);
    head_kernel<<<NR / 80, 320>>>(out);
}

// round 4
// speedup vs baseline: 1.1671x; 1.1671x over previous
#include <cuda_runtime.h>
#include <cstdint>

typedef unsigned long long ull;

#define NR 50000      // rows (N)
#define HH 4          // heads
#define DM 256        // D_MODEL
#define DHEAD 1024    // H * D_MODEL
#define NCLS 40       // classes

#define PITCH 42                      // smem row pitch (words), even for 8B pairs
#define U_WORDS (DHEAD * PITCH)       // 43008 floats = 172032 B
#define WG_WORDS (128 * NCLS * 2)     // dup'd ull chunk as 2 words each = 10240 floats
#define SMEM_BYTES ((U_WORDS + WG_WORDS) * 4)   // 212992 B

// Static device scratch (no cudaMalloc allowed)
__device__ float g_w[HH * NR];         // perm value scattered by column, per head
__device__ float g_wgk[DHEAD * NCLS];  // gamma[k] * W_head[k][o]
__device__ float g_cvec[NCLS];         // beta @ W_head + b_head

__device__ __forceinline__ ull dup2(float x) {
    ull r; asm("mov.b64 %0, {%1, %1};" : "=l"(r) : "f"(x)); return r;
}
__device__ __forceinline__ void unpk(ull v, float& a, float& b) {
    asm("mov.b64 {%0, %1}, %2;" : "=f"(a), "=f"(b) : "l"(v));
}
__device__ __forceinline__ void fma2(ull& acc, ull a, ull b) {
    asm("fma.rn.f32x2 %0, %1, %2, %0;" : "+l"(acc) : "l"(a), "l"(b));
}

// ---------------------------------------------------------------------------
// prep: scatter perm values by COLUMN index; fold gamma into W_head.
// ---------------------------------------------------------------------------
__global__ void prep_kernel(const int* __restrict__ idx, const float* __restrict__ vals,
                            const float* __restrict__ gamma, const float* __restrict__ Wh) {
    int t = blockIdx.x * blockDim.x + threadIdx.x;
    const int NNZ = HH * NR;
    if (t < NNZ) {
        int b = idx[t];
        int j = idx[2 * NNZ + t];
        g_w[b * NR + j] = vals[t];
    }
    if (t < DHEAD * NCLS) {
        g_wgk[t] = gamma[t / NCLS] * Wh[t];
    }
}

// ---------------------------------------------------------------------------
// cvec: g_cvec[o] = beta @ W_head[:,o] + b_head[o]
// ---------------------------------------------------------------------------
__global__ void cvec_kernel(const float* __restrict__ beta, const float* __restrict__ Wh,
                            const float* __restrict__ bh) {
    const int o = blockIdx.x, t = threadIdx.x;
    float s = 0.f;
    for (int k = t; k < DHEAD; k += 256) s += beta[k] * Wh[k * NCLS + o];
    #pragma unroll
    for (int off = 16; off; off >>= 1) s += __shfl_xor_sync(~0u, s, off);
    __shared__ float red[8];
    if ((t & 31) == 0) red[t >> 5] = s;
    __syncthreads();
    if (t == 0) {
        float tot = bh[o];
        #pragma unroll
        for (int w = 0; w < 8; w++) tot += red[w];
        g_cvec[o] = tot;
    }
}

// ---------------------------------------------------------------------------
// fused: 40 rows/block, 256 threads, one kernel end-to-end.
//   P1: Z = feat @ W_in (thread = 2 cols x 20 rows, f32x2 row pairs)
//   P2: LN stats over the 1024-wide concat
//   P3: normalized u (fp32, exact) -> smem [k][r], overlaying feat tile
//   P4: head GEMM 40x40x1024 from smem, dup'd weights staged in 128-k chunks
// ---------------------------------------------------------------------------
__global__ __launch_bounds__(256, 1) void fused_kernel(
    const float* __restrict__ features, const float* __restrict__ appd,
    const float* __restrict__ Win, const float* __restrict__ bin,
    float* __restrict__ out)
{
    extern __shared__ float smem[];
    float* u_s = smem;                         // [k][r], pitch 42; front 256 rows double as feat tile
    ull*   wgd_s = (ull*)(smem + U_WORDS);     // dup'd (w,w) head-weight chunk [128][40]

    __shared__ float w_s[4 * 40];
    __shared__ float redS[8][20], redQ[8][20];
    __shared__ float mu_s[40], rs_s[40];

    const int t = threadIdx.x;
    const int j0 = blockIdx.x * 40;

    // ---- load feat tile transposed into u_s[k][r]: k<128 features, k>=128 appd ----
    {
        const float* src = (t < 128) ? (features + (size_t)j0 * 128 + t)
                                     : (appd + (size_t)j0 * 128 + (t - 128));
        #pragma unroll
        for (int r = 0; r < 40; r++)
            u_s[t * PITCH + r] = src[(size_t)r * 128];
    }
    if (t < 160) w_s[t] = g_w[(t / 40) * NR + j0 + (t % 40)];
    __syncthreads();

    const int cp = t & 127;      // col pair: cols 2cp, 2cp+1
    const int rh = t >> 7;       // row half: rows rh*20 .. rh*20+19

    // ---- P1: Z-GEMM ----
    ull acc0[10], acc1[10];
    #pragma unroll
    for (int p = 0; p < 10; p++) { acc0[p] = 0ULL; acc1[p] = 0ULL; }

    const float* fb = u_s + rh * 20;
    #pragma unroll 8
    for (int k = 0; k < 256; k++) {
        float2 wv = *reinterpret_cast<const float2*>(Win + k * 256 + 2 * cp);
        ull w0 = dup2(wv.x), w1 = dup2(wv.y);
        const ull* fp = reinterpret_cast<const ull*>(fb + k * PITCH);
        #pragma unroll
        for (int p = 0; p < 10; p++) {
            ull f = fp[p];
            fma2(acc0[p], f, w0);
            fma2(acc1[p], f, w1);
        }
    }

    const float2 bi = *reinterpret_cast<const float2*>(bin + 2 * cp);
    const int lane = t & 31, wid = t >> 5;

    // ---- P2: LN stats ----
    #pragma unroll
    for (int p = 0; p < 10; p++) {
        float z00, z01, z10, z11;
        unpk(acc0[p], z00, z01);
        unpk(acc1[p], z10, z11);
        #pragma unroll
        for (int sub = 0; sub < 2; sub++) {
            const int rl = 2 * p + sub;
            const float zc0 = sub ? z01 : z00;
            const float zc1 = sub ? z11 : z10;
            float s = 0.f, q = 0.f;
            #pragma unroll
            for (int h = 0; h < 4; h++) {
                float w = w_s[h * 40 + rh * 20 + rl];
                float u0 = w * fmaxf(fmaf(w, zc0, bi.x), 0.f);
                float u1 = w * fmaxf(fmaf(w, zc1, bi.y), 0.f);
                s += u0 + u1; q += u0 * u0 + u1 * u1;
            }
            #pragma unroll
            for (int o = 16; o; o >>= 1) {
                s += __shfl_xor_sync(~0u, s, o);
                q += __shfl_xor_sync(~0u, q, o);
            }
            if (lane == 0) { redS[wid][rl] = s; redQ[wid][rl] = q; }
        }
    }
    __syncthreads();
    if (t < 40) {
        const int w0 = (t < 20) ? 0 : 4;
        const int i = (t < 20) ? t : t - 20;
        float s = redS[w0][i] + redS[w0 + 1][i] + redS[w0 + 2][i] + redS[w0 + 3][i];
        float q = redQ[w0][i] + redQ[w0 + 1][i] + redQ[w0 + 2][i] + redQ[w0 + 3][i];
        float mu = s * (1.f / 1024.f);
        float var = q * (1.f / 1024.f) - mu * mu;
        mu_s[t] = mu;
        rs_s[t] = rsqrtf(var + 1e-5f);
    }
    __syncthreads();

    // ---- P3: write normalized u (fp32) into u_s[k][r], row pairs as float2 ----
    #pragma unroll
    for (int p = 0; p < 10; p++) {
        float z00, z01, z10, z11;
        unpk(acc0[p], z00, z01);   // col 2cp, rows r0, r0+1
        unpk(acc1[p], z10, z11);   // col 2cp+1
        const int r0 = rh * 20 + 2 * p;
        const float mu0 = mu_s[r0], rs0 = rs_s[r0];
        const float mu1 = mu_s[r0 + 1], rs1 = rs_s[r0 + 1];
        #pragma unroll
        for (int h = 0; h < 4; h++) {
            float wa = w_s[h * 40 + r0];
            float wb = w_s[h * 40 + r0 + 1];
            // col even (2cp)
            float ue0 = wa * fmaxf(fmaf(wa, z00, bi.x), 0.f);
            float ue1 = wb * fmaxf(fmaf(wb, z01, bi.x), 0.f);
            // col odd (2cp+1)
            float uo0 = wa * fmaxf(fmaf(wa, z10, bi.y), 0.f);
            float uo1 = wb * fmaxf(fmaf(wb, z11, bi.y), 0.f);
            const int k0 = h * 256 + 2 * cp;
            *reinterpret_cast<float2*>(&u_s[k0 * PITCH + r0]) =
                make_float2((ue0 - mu0) * rs0, (ue1 - mu1) * rs1);
            *reinterpret_cast<float2*>(&u_s[(k0 + 1) * PITCH + r0]) =
                make_float2((uo0 - mu0) * rs0, (uo1 - mu1) * rs1);
        }
    }

    // ---- P4: head GEMM: out[r][o] = sum_k u_s[k][r] * wgk[k][o] + cvec[o] ----
    const int o2 = t % 20;       // cols 2*o2, 2*o2+1
    const int rg = t / 20;       // rows rg*4 .. rg*4+3 (2 f32x2 pairs); active t<200
    ull a00 = 0, a01 = 0, a10 = 0, a11 = 0;

    for (int kc = 0; kc < DHEAD / 128; kc++) {
        __syncthreads();
        // stage dup'd head-weight chunk (all 256 threads)
        #pragma unroll
        for (int i = 0; i < 20; i++)
            wgd_s[t + 256 * i] = dup2(g_wgk[(size_t)kc * 128 * NCLS + t + 256 * i]);
        __syncthreads();

        if (t < 200) {
            const float* ub = u_s + (size_t)kc * 128 * PITCH + rg * 4;
            #pragma unroll 4
            for (int kk = 0; kk < 128; kk++) {
                ull w0 = wgd_s[kk * NCLS + 2 * o2];
                ull w1 = wgd_s[kk * NCLS + 2 * o2 + 1];
                const ull* up = reinterpret_cast<const ull*>(ub + kk * PITCH);
                ull u0 = up[0], u1 = up[1];
                fma2(a00, u0, w0);
                fma2(a01, u1, w0);
                fma2(a10, u0, w1);
                fma2(a11, u1, w1);
            }
        }
    }

    if (t < 200) {
        const float2 cv = *reinterpret_cast<const float2*>(g_cvec + 2 * o2);
        float e0, e1, e2, e3, d0, d1, d2, d3;
        unpk(a00, e0, e1);   // col even, rows rg*4, rg*4+1
        unpk(a01, e2, e3);   // col even, rows rg*4+2, rg*4+3
        unpk(a10, d0, d1);   // col odd
        unpk(a11, d2, d3);
        const size_t r0 = (size_t)(j0 + rg * 4);
        float* o0 = out + r0 * NCLS + 2 * o2;
        *reinterpret_cast<float2*>(o0)            = make_float2(e0 + cv.x, d0 + cv.y);
        *reinterpret_cast<float2*>(o0 + NCLS)     = make_float2(e1 + cv.x, d1 + cv.y);
        *reinterpret_cast<float2*>(o0 + 2 * NCLS) = make_float2(e2 + cv.x, d2 + cv.y);
        *reinterpret_cast<float2*>(o0 + 3 * NCLS) = make_float2(e3 + cv.x, d3 + cv.y);
    }
}

// ---------------------------------------------------------------------------
extern "C" void kernel_launch(void* const* d_in, const int* in_sizes, int n_in,
                              void* d_out, int out_size) {
    const int*   perm_idx  = (const int*)d_in[0];
    const float* perm_vals = (const float*)d_in[1];
    const float* features  = (const float*)d_in[2];
    const float* appd      = (const float*)d_in[3];
    const float* Win       = (const float*)d_in[4];
    const float* bin       = (const float*)d_in[5];
    const float* gamma     = (const float*)d_in[6];
    const float* beta      = (const float*)d_in[7];
    const float* Whead     = (const float*)d_in[8];
    const float* bhead     = (const float*)d_in[9];
    float* out = (float*)d_out;

    static bool attr_set = false;
    if (!attr_set) {
        cudaFuncSetAttribute(fused_kernel, cudaFuncAttributeMaxDynamicSharedMemorySize,
                             SMEM_BYTES);
        attr_set = true;
    }

    prep_kernel<<<(HH * NR + 255) / 256, 256>>>(perm_idx, perm_vals, gamma, Whead);
    cvec_kernel<<<NCLS, 256>>>(beta, Whead, bhead);
    fused_kernel<<<NR / 40, 256, SMEM_BYTES>>>(features, appd, Win, bin, out);
}